// round 4
// baseline (speedup 1.0000x reference)
#include <cuda_runtime.h>
#include <cstdint>

// Problem constants (fixed by the dataset)
#define NN   50000
#define EE   800000
#define CC   128
#define HEADS 4
#define HEAD_DIM 32
#define INV_SQRT_HD 0.17677669529663687f   // 1/sqrt(32)
#define LN_EPS 1e-5f

// ---------------- device scratch (static, no allocation) ----------------
__device__ float g_q[NN * CC];          // q, pre-scaled by 1/sqrt(Hd)   (25.6 MB)
__device__ float g_kv[NN * 2 * CC];     // interleaved [k(128) | v(128)] per node (51.2 MB)
__device__ float g_attnout[NN * CC];    // attention output               (25.6 MB)
__device__ int   g_deg[NN];
__device__ int   g_cur[NN];
__device__ int   g_off[NN + 1];
__device__ int   g_edges[EE];           // packed: src | (structure_type << 24)

// ---------------- zero counters ----------------
__global__ void zero_kernel() {
    int i = blockIdx.x * blockDim.x + threadIdx.x;
    if (i < NN) { g_deg[i] = 0; g_cur[i] = 0; }
}

// ---------------- histogram over dst ----------------
__global__ void hist_kernel(const int* __restrict__ ei) {
    int e = blockIdx.x * blockDim.x + threadIdx.x;
    if (e < EE) atomicAdd(&g_deg[ei[EE + e]], 1);
}

// ---------------- single-block exclusive scan of g_deg -> g_off ----------------
__global__ void scan_kernel() {
    __shared__ int wsum[32];
    __shared__ int s_carry;
    const int tid = threadIdx.x, lane = tid & 31, wid = tid >> 5;
    int carry = 0;
    for (int base = 0; base < NN; base += 1024) {
        int i = base + tid;
        int v = (i < NN) ? g_deg[i] : 0;
        int inc = v;
        #pragma unroll
        for (int d = 1; d < 32; d <<= 1) {
            int t = __shfl_up_sync(0xffffffffu, inc, d);
            if (lane >= d) inc += t;
        }
        if (lane == 31) wsum[wid] = inc;
        __syncthreads();
        if (wid == 0) {
            int w = wsum[lane];
            int wi = w;
            #pragma unroll
            for (int d = 1; d < 32; d <<= 1) {
                int t = __shfl_up_sync(0xffffffffu, wi, d);
                if (lane >= d) wi += t;
            }
            wsum[lane] = wi - w;   // exclusive warp offset
        }
        __syncthreads();
        int excl = carry + wsum[wid] + inc - v;
        if (i < NN) g_off[i] = excl;
        if (tid == 1023) s_carry = excl + v;
        __syncthreads();
        carry = s_carry;
    }
    if (tid == 0) g_off[NN] = carry;   // == EE
}

// ---------------- scatter edges into CSR (by dst), pack src+stype ----------------
__global__ void scatter_kernel(const int* __restrict__ ei,
                               const int* __restrict__ stype) {
    int e = blockIdx.x * blockDim.x + threadIdx.x;
    if (e >= EE) return;
    int s = ei[e];
    int d = ei[EE + e];
    int pos = atomicAdd(&g_cur[d], 1);
    g_edges[g_off[d] + pos] = s | (stype[s] << 24);
}

// ---------------- tiled fp32 SGEMM: dst[r,c] = (sum_k A[r,k]W[k,c] + bias[c]) * scale
// Destination is one of the device-global scratch buffers (dst_sel), so the
// host never needs cudaGetSymbolAddress.
// BM=64, BN=128(=Cout), BK=16, 256 threads, TM=4, TN=8
__global__ __launch_bounds__(256)
void sgemm128_kernel(const float* __restrict__ A,
                     const float* __restrict__ W,
                     const float* __restrict__ bias,
                     int dst_sel, int ostride, float scale) {
    float* out = (dst_sel == 0) ? g_q : (dst_sel == 1) ? g_kv : (g_kv + 128);

    __shared__ float As[16][68];     // padded
    __shared__ float Bs[16][128];
    const int tid = threadIdx.x;
    const int tx = tid & 15;         // col group (8 cols)
    const int ty = tid >> 4;         // row group (4 rows)
    const int row0 = blockIdx.x * 64;

    const int arow  = tid >> 2;          // 0..63
    const int acol4 = (tid & 3) * 4;     // 0,4,8,12
    const int brow  = tid >> 5;          // 0..7
    const int bcol  = (tid & 31) * 4;    // 0..124

    float acc[4][8];
    #pragma unroll
    for (int i = 0; i < 4; i++)
        #pragma unroll
        for (int j = 0; j < 8; j++) acc[i][j] = 0.f;

    for (int kk = 0; kk < 128; kk += 16) {
        float4 av = make_float4(0.f, 0.f, 0.f, 0.f);
        int gr = row0 + arow;
        if (gr < NN) av = *(const float4*)&A[gr * 128 + kk + acol4];
        As[acol4 + 0][arow] = av.x;
        As[acol4 + 1][arow] = av.y;
        As[acol4 + 2][arow] = av.z;
        As[acol4 + 3][arow] = av.w;
        *(float4*)&Bs[brow][bcol]     = *(const float4*)&W[(kk + brow) * 128 + bcol];
        *(float4*)&Bs[brow + 8][bcol] = *(const float4*)&W[(kk + brow + 8) * 128 + bcol];
        __syncthreads();
        #pragma unroll
        for (int k = 0; k < 16; k++) {
            float4 a  = *(const float4*)&As[k][ty * 4];
            float4 b0 = *(const float4*)&Bs[k][tx * 8];
            float4 b1 = *(const float4*)&Bs[k][tx * 8 + 4];
            float ar[4] = {a.x, a.y, a.z, a.w};
            float br[8] = {b0.x, b0.y, b0.z, b0.w, b1.x, b1.y, b1.z, b1.w};
            #pragma unroll
            for (int i = 0; i < 4; i++)
                #pragma unroll
                for (int j = 0; j < 8; j++)
                    acc[i][j] += ar[i] * br[j];
        }
        __syncthreads();
    }

    float4 bb0 = *(const float4*)&bias[tx * 8];
    float4 bb1 = *(const float4*)&bias[tx * 8 + 4];
    float bcol8[8] = {bb0.x, bb0.y, bb0.z, bb0.w, bb1.x, bb1.y, bb1.z, bb1.w};
    #pragma unroll
    for (int i = 0; i < 4; i++) {
        int r = row0 + ty * 4 + i;
        if (r >= NN) continue;
        float4 o0, o1;
        o0.x = (acc[i][0] + bcol8[0]) * scale;
        o0.y = (acc[i][1] + bcol8[1]) * scale;
        o0.z = (acc[i][2] + bcol8[2]) * scale;
        o0.w = (acc[i][3] + bcol8[3]) * scale;
        o1.x = (acc[i][4] + bcol8[4]) * scale;
        o1.y = (acc[i][5] + bcol8[5]) * scale;
        o1.z = (acc[i][6] + bcol8[6]) * scale;
        o1.w = (acc[i][7] + bcol8[7]) * scale;
        *(float4*)&out[r * ostride + tx * 8]     = o0;
        *(float4*)&out[r * ostride + tx * 8 + 4] = o1;
    }
}

// ---------------- fused edge attention: one warp per dst node ----------------
// out[dst] = (sum_e exp(q.k + bias) * v[src]) / (sum_e exp(...) + 1e-16)
__global__ __launch_bounds__(256)
void attn_kernel(const float* __restrict__ sbias) {
    int node = (blockIdx.x * blockDim.x + threadIdx.x) >> 5;
    if (node >= NN) return;
    const int lane = threadIdx.x & 31;
    const int head = lane >> 3;

    const float4 qv = ((const float4*)g_q)[node * 32 + lane];
    const int beg = g_off[node], end = g_off[node + 1];

    float s = 0.f;
    float4 acc = make_float4(0.f, 0.f, 0.f, 0.f);

    for (int i = beg; i < end; i++) {
        int p = g_edges[i];
        int src = p & 0x00FFFFFF;
        int st  = p >> 24;
        const float4* kvp = (const float4*)g_kv + src * 64;
        float4 kvv = kvp[lane];        // k slice
        float4 vv  = kvp[32 + lane];   // v slice
        float d = qv.x * kvv.x + qv.y * kvv.y + qv.z * kvv.z + qv.w * kvv.w;
        d += __shfl_xor_sync(0xffffffffu, d, 1);
        d += __shfl_xor_sync(0xffffffffu, d, 2);
        d += __shfl_xor_sync(0xffffffffu, d, 4);   // full head dot on all 8 lanes
        float e = __expf(d + __ldg(&sbias[st * HEADS + head]));
        s += e;
        acc.x += e * vv.x; acc.y += e * vv.y;
        acc.z += e * vv.z; acc.w += e * vv.w;
    }
    float inv = 1.f / (s + 1e-16f);
    float4 o = make_float4(acc.x * inv, acc.y * inv, acc.z * inv, acc.w * inv);
    ((float4*)g_attnout)[node * 32 + lane] = o;
}

// ---------------- final: y = attnout@Wo + bo + x ; LayerNorm(y) -> out ----------------
__global__ __launch_bounds__(256)
void sgemm_ln_kernel(const float* __restrict__ Wo,
                     const float* __restrict__ bo,
                     const float* __restrict__ X,
                     const float* __restrict__ gamma,
                     const float* __restrict__ beta,
                     float* __restrict__ out) {
    __shared__ float As[16][68];
    __shared__ float Bs[16][128];
    __shared__ float Ys[64][132];
    const float* A = g_attnout;
    const int tid = threadIdx.x;
    const int tx = tid & 15;
    const int ty = tid >> 4;
    const int row0 = blockIdx.x * 64;

    const int arow  = tid >> 2;
    const int acol4 = (tid & 3) * 4;
    const int brow  = tid >> 5;
    const int bcol  = (tid & 31) * 4;

    float acc[4][8];
    #pragma unroll
    for (int i = 0; i < 4; i++)
        #pragma unroll
        for (int j = 0; j < 8; j++) acc[i][j] = 0.f;

    for (int kk = 0; kk < 128; kk += 16) {
        float4 av = make_float4(0.f, 0.f, 0.f, 0.f);
        int gr = row0 + arow;
        if (gr < NN) av = *(const float4*)&A[gr * 128 + kk + acol4];
        As[acol4 + 0][arow] = av.x;
        As[acol4 + 1][arow] = av.y;
        As[acol4 + 2][arow] = av.z;
        As[acol4 + 3][arow] = av.w;
        *(float4*)&Bs[brow][bcol]     = *(const float4*)&Wo[(kk + brow) * 128 + bcol];
        *(float4*)&Bs[brow + 8][bcol] = *(const float4*)&Wo[(kk + brow + 8) * 128 + bcol];
        __syncthreads();
        #pragma unroll
        for (int k = 0; k < 16; k++) {
            float4 a  = *(const float4*)&As[k][ty * 4];
            float4 b0 = *(const float4*)&Bs[k][tx * 8];
            float4 b1 = *(const float4*)&Bs[k][tx * 8 + 4];
            float ar[4] = {a.x, a.y, a.z, a.w};
            float br[8] = {b0.x, b0.y, b0.z, b0.w, b1.x, b1.y, b1.z, b1.w};
            #pragma unroll
            for (int i = 0; i < 4; i++)
                #pragma unroll
                for (int j = 0; j < 8; j++)
                    acc[i][j] += ar[i] * br[j];
        }
        __syncthreads();
    }

    // y = acc + bo + residual  -> smem
    float4 bb0 = *(const float4*)&bo[tx * 8];
    float4 bb1 = *(const float4*)&bo[tx * 8 + 4];
    float bcol8[8] = {bb0.x, bb0.y, bb0.z, bb0.w, bb1.x, bb1.y, bb1.z, bb1.w};
    #pragma unroll
    for (int i = 0; i < 4; i++) {
        int rr = ty * 4 + i;
        int r = row0 + rr;
        float4 x0 = make_float4(0.f, 0.f, 0.f, 0.f), x1 = x0;
        if (r < NN) {
            x0 = *(const float4*)&X[r * 128 + tx * 8];
            x1 = *(const float4*)&X[r * 128 + tx * 8 + 4];
        }
        Ys[rr][tx * 8 + 0] = acc[i][0] + bcol8[0] + x0.x;
        Ys[rr][tx * 8 + 1] = acc[i][1] + bcol8[1] + x0.y;
        Ys[rr][tx * 8 + 2] = acc[i][2] + bcol8[2] + x0.z;
        Ys[rr][tx * 8 + 3] = acc[i][3] + bcol8[3] + x0.w;
        Ys[rr][tx * 8 + 4] = acc[i][4] + bcol8[4] + x1.x;
        Ys[rr][tx * 8 + 5] = acc[i][5] + bcol8[5] + x1.y;
        Ys[rr][tx * 8 + 6] = acc[i][6] + bcol8[6] + x1.z;
        Ys[rr][tx * 8 + 7] = acc[i][7] + bcol8[7] + x1.w;
    }
    __syncthreads();

    // LayerNorm: 8 warps, 8 rows each
    const int w = tid >> 5, lane = tid & 31;
    float4 g  = *(const float4*)&gamma[lane * 4];
    float4 bt = *(const float4*)&beta[lane * 4];
    #pragma unroll 1
    for (int rr = w * 8; rr < w * 8 + 8; rr++) {
        int r = row0 + rr;
        if (r >= NN) continue;
        float4 yv = *(const float4*)&Ys[rr][lane * 4];
        float s1 = yv.x + yv.y + yv.z + yv.w;
        float s2 = yv.x * yv.x + yv.y * yv.y + yv.z * yv.z + yv.w * yv.w;
        #pragma unroll
        for (int m = 16; m >= 1; m >>= 1) {
            s1 += __shfl_xor_sync(0xffffffffu, s1, m);
            s2 += __shfl_xor_sync(0xffffffffu, s2, m);
        }
        float mean = s1 * (1.f / 128.f);
        float var  = s2 * (1.f / 128.f) - mean * mean;
        float rstd = rsqrtf(var + LN_EPS);
        float4 o;
        o.x = (yv.x - mean) * rstd * g.x + bt.x;
        o.y = (yv.y - mean) * rstd * g.y + bt.y;
        o.z = (yv.z - mean) * rstd * g.z + bt.z;
        o.w = (yv.w - mean) * rstd * g.w + bt.w;
        *(float4*)&out[r * 128 + lane * 4] = o;
    }
}

// ---------------- launch ----------------
extern "C" void kernel_launch(void* const* d_in, const int* in_sizes, int n_in,
                              void* d_out, int out_size) {
    const float* x      = (const float*)d_in[0];
    const int*   stype  = (const int*)  d_in[1];
    const int*   ei     = (const int*)  d_in[2];
    const float* Wq     = (const float*)d_in[3];
    const float* bq     = (const float*)d_in[4];
    const float* Wk     = (const float*)d_in[5];
    const float* bk     = (const float*)d_in[6];
    const float* Wv     = (const float*)d_in[7];
    const float* bv     = (const float*)d_in[8];
    const float* sbias  = (const float*)d_in[9];
    const float* Wo     = (const float*)d_in[10];
    const float* bo     = (const float*)d_in[11];
    const float* gamma  = (const float*)d_in[12];
    const float* beta   = (const float*)d_in[13];
    float* out = (float*)d_out;

    const int gemm_blocks = (NN + 63) / 64;
    const int edge_blocks = (EE + 255) / 256;
    const int node_blocks = (NN + 255) / 256;

    // CSR build
    zero_kernel<<<node_blocks, 256>>>();
    hist_kernel<<<edge_blocks, 256>>>(ei);
    scan_kernel<<<1, 1024>>>();
    scatter_kernel<<<edge_blocks, 256>>>(ei, stype);

    // QKV projections (q pre-scaled by 1/sqrt(Hd); k,v interleaved per node)
    sgemm128_kernel<<<gemm_blocks, 256>>>(x, Wq, bq, 0, 128, INV_SQRT_HD);
    sgemm128_kernel<<<gemm_blocks, 256>>>(x, Wk, bk, 1, 256, 1.f);
    sgemm128_kernel<<<gemm_blocks, 256>>>(x, Wv, bv, 2, 256, 1.f);

    // fused segment softmax + aggregation (warp per dst node)
    attn_kernel<<<(NN * 32 + 255) / 256, 256>>>(sbias);

    // output projection + residual + layernorm
    sgemm_ln_kernel<<<gemm_blocks, 256>>>(Wo, bo, x, gamma, beta, out);
}

// round 5
// speedup vs baseline: 1.1468x; 1.1468x over previous
#include <cuda_runtime.h>
#include <cstdint>

// Problem constants (fixed by the dataset)
#define NN   50000
#define EE   800000
#define CC   128
#define HEADS 4
#define HEAD_DIM 32
#define INV_SQRT_HD 0.17677669529663687f   // 1/sqrt(32)
#define LN_EPS 1e-5f

typedef unsigned long long ull;

// ---------------- device scratch (static, no allocation) ----------------
__device__ float g_q[NN * CC];          // q, pre-scaled by 1/sqrt(Hd)
__device__ float g_kv[NN * 2 * CC];     // interleaved [k(128) | v(128)] per node
__device__ float g_attnout[NN * CC];    // attention output
__device__ int   g_deg[NN];
__device__ int   g_cur[NN];
__device__ int   g_off[NN + 1];
__device__ int   g_edges[EE];           // packed: src | (structure_type << 24)

// ---------------- packed f32x2 helpers ----------------
__device__ __forceinline__ ull pack2(float lo, float hi) {
    ull r;
    asm("mov.b64 %0, {%1, %2};" : "=l"(r) : "f"(lo), "f"(hi));
    return r;
}
__device__ __forceinline__ float2 unpack2(ull v) {
    float2 r;
    asm("mov.b64 {%0, %1}, %2;" : "=f"(r.x), "=f"(r.y) : "l"(v));
    return r;
}
__device__ __forceinline__ void ffma2(ull &acc, ull a, ull b) {
    asm("fma.rn.f32x2 %0, %1, %2, %0;" : "+l"(acc) : "l"(a), "l"(b));
}

// ---------------- zero counters ----------------
__global__ void zero_kernel() {
    int i = blockIdx.x * blockDim.x + threadIdx.x;
    if (i < NN) { g_deg[i] = 0; g_cur[i] = 0; }
}

// ---------------- histogram over dst ----------------
__global__ void hist_kernel(const int* __restrict__ ei) {
    int e = blockIdx.x * blockDim.x + threadIdx.x;
    if (e < EE) atomicAdd(&g_deg[ei[EE + e]], 1);
}

// ---------------- single-block exclusive scan of g_deg -> g_off ----------------
__global__ void scan_kernel() {
    __shared__ int wsum[32];
    __shared__ int s_carry;
    const int tid = threadIdx.x, lane = tid & 31, wid = tid >> 5;
    int carry = 0;
    for (int base = 0; base < NN; base += 1024) {
        int i = base + tid;
        int v = (i < NN) ? g_deg[i] : 0;
        int inc = v;
        #pragma unroll
        for (int d = 1; d < 32; d <<= 1) {
            int t = __shfl_up_sync(0xffffffffu, inc, d);
            if (lane >= d) inc += t;
        }
        if (lane == 31) wsum[wid] = inc;
        __syncthreads();
        if (wid == 0) {
            int w = wsum[lane];
            int wi = w;
            #pragma unroll
            for (int d = 1; d < 32; d <<= 1) {
                int t = __shfl_up_sync(0xffffffffu, wi, d);
                if (lane >= d) wi += t;
            }
            wsum[lane] = wi - w;   // exclusive warp offset
        }
        __syncthreads();
        int excl = carry + wsum[wid] + inc - v;
        if (i < NN) g_off[i] = excl;
        if (tid == 1023) s_carry = excl + v;
        __syncthreads();
        carry = s_carry;
    }
    if (tid == 0) g_off[NN] = carry;   // == EE
}

// ---------------- scatter edges into CSR (by dst), pack src+stype ----------------
__global__ void scatter_kernel(const int* __restrict__ ei,
                               const int* __restrict__ stype) {
    int e = blockIdx.x * blockDim.x + threadIdx.x;
    if (e >= EE) return;
    int s = ei[e];
    int d = ei[EE + e];
    int pos = atomicAdd(&g_cur[d], 1);
    g_edges[g_off[d] + pos] = s | (stype[s] << 24);
}

// ============================================================================
// GEMM core (shared by both GEMM kernels):
// BM=128, BN=128, BK=16, 256 threads. TM=8 (rows), TN=8 (cols) per thread.
// Inner product via packed fma.rn.f32x2: A duplicated in smem so (a,a) packed
// operands are direct LDS; B pairs are natural adjacent floats.
// tx = tid&15 -> cols tx*8..+7 ; ty = tid>>4 -> rows ty*8..+7
// ============================================================================
#define AS2_STRIDE 264   // 256 floats needed + pad (keeps 16B alignment)

struct GemmFrag {
    ull acc[8][4];   // [row i][col pair jp]
};

__device__ __forceinline__ void gemm_mainloop(
    const float* __restrict__ A, const float* __restrict__ W,
    int row0, GemmFrag& F,
    float (*As2)[AS2_STRIDE], float (*Bs)[128])
{
    const int tid = threadIdx.x;
    const int tx = tid & 15;
    const int ty = tid >> 4;
    const int arow  = tid >> 1;          // 0..127
    const int acol8 = (tid & 1) * 8;     // 0 or 8
    const int brow  = tid >> 5;          // 0..7
    const int bcol  = (tid & 31) * 4;    // 0..124

    #pragma unroll
    for (int i = 0; i < 8; i++)
        #pragma unroll
        for (int j = 0; j < 4; j++) F.acc[i][j] = 0ull;

    for (int kk = 0; kk < 128; kk += 16) {
        // ---- load A tile (128 rows x 16 k), store duplicated+transposed ----
        float av[8];
        #pragma unroll
        for (int j = 0; j < 8; j++) av[j] = 0.f;
        int gr = row0 + arow;
        if (gr < NN) {
            float4 a0 = *(const float4*)&A[gr * 128 + kk + acol8];
            float4 a1 = *(const float4*)&A[gr * 128 + kk + acol8 + 4];
            av[0] = a0.x; av[1] = a0.y; av[2] = a0.z; av[3] = a0.w;
            av[4] = a1.x; av[5] = a1.y; av[6] = a1.z; av[7] = a1.w;
        }
        #pragma unroll
        for (int j = 0; j < 8; j++) {
            *(ull*)&As2[acol8 + j][2 * arow] = pack2(av[j], av[j]);
        }
        // ---- load B tile (16 k x 128 cols) ----
        *(float4*)&Bs[brow][bcol]     = *(const float4*)&W[(kk + brow) * 128 + bcol];
        *(float4*)&Bs[brow + 8][bcol] = *(const float4*)&W[(kk + brow + 8) * 128 + bcol];
        __syncthreads();

        #pragma unroll
        for (int k = 0; k < 16; k++) {
            const ulonglong2* ap = (const ulonglong2*)&As2[k][ty * 16];
            ulonglong2 a01 = ap[0], a23 = ap[1], a45 = ap[2], a67 = ap[3];
            const ulonglong2* bp = (const ulonglong2*)&Bs[k][tx * 8];
            ulonglong2 b01 = bp[0], b23 = bp[1];
            ull ad[8] = {a01.x, a01.y, a23.x, a23.y, a45.x, a45.y, a67.x, a67.y};
            ull bd[4] = {b01.x, b01.y, b23.x, b23.y};
            #pragma unroll
            for (int i = 0; i < 8; i++)
                #pragma unroll
                for (int jp = 0; jp < 4; jp++)
                    ffma2(F.acc[i][jp], ad[i], bd[jp]);
        }
        __syncthreads();
    }
}

// ---------------- QKV projection GEMM -> device scratch ----------------
__global__ __launch_bounds__(256)
void sgemm128_kernel(const float* __restrict__ A,
                     const float* __restrict__ W,
                     const float* __restrict__ bias,
                     int dst_sel, int ostride, float scale) {
    float* out = (dst_sel == 0) ? g_q : (dst_sel == 1) ? g_kv : (g_kv + 128);
    __shared__ float As2[16][AS2_STRIDE];
    __shared__ float Bs[16][128];

    const int tid = threadIdx.x;
    const int tx = tid & 15;
    const int ty = tid >> 4;
    const int row0 = blockIdx.x * 128;

    GemmFrag F;
    gemm_mainloop(A, W, row0, F, As2, Bs);

    float4 bb0 = *(const float4*)&bias[tx * 8];
    float4 bb1 = *(const float4*)&bias[tx * 8 + 4];
    #pragma unroll
    for (int i = 0; i < 8; i++) {
        int r = row0 + ty * 8 + i;
        if (r >= NN) continue;
        float2 p0 = unpack2(F.acc[i][0]);
        float2 p1 = unpack2(F.acc[i][1]);
        float2 p2 = unpack2(F.acc[i][2]);
        float2 p3 = unpack2(F.acc[i][3]);
        float4 o0, o1;
        o0.x = (p0.x + bb0.x) * scale;
        o0.y = (p0.y + bb0.y) * scale;
        o0.z = (p1.x + bb0.z) * scale;
        o0.w = (p1.y + bb0.w) * scale;
        o1.x = (p2.x + bb1.x) * scale;
        o1.y = (p2.y + bb1.y) * scale;
        o1.z = (p3.x + bb1.z) * scale;
        o1.w = (p3.y + bb1.w) * scale;
        *(float4*)&out[r * ostride + tx * 8]     = o0;
        *(float4*)&out[r * ostride + tx * 8 + 4] = o1;
    }
}

// ---------------- fused edge attention: one warp per dst node ----------------
__global__ __launch_bounds__(256)
void attn_kernel(const float* __restrict__ sbias) {
    int node = (blockIdx.x * blockDim.x + threadIdx.x) >> 5;
    if (node >= NN) return;
    const int lane = threadIdx.x & 31;
    const int head = lane >> 3;

    // preload structure bias for this head (S_TYPES = 3)
    const float sb0 = __ldg(&sbias[0 * HEADS + head]);
    const float sb1 = __ldg(&sbias[1 * HEADS + head]);
    const float sb2 = __ldg(&sbias[2 * HEADS + head]);

    const float4 qv = ((const float4*)g_q)[node * 32 + lane];
    const int beg = g_off[node], end = g_off[node + 1];

    float s = 0.f;
    float4 acc = make_float4(0.f, 0.f, 0.f, 0.f);

    int i = beg;
    for (; i + 2 <= end; i += 2) {
        int p0 = g_edges[i];
        int p1 = g_edges[i + 1];
        const float4* kp0 = (const float4*)g_kv + (ull)(p0 & 0x00FFFFFF) * 64;
        const float4* kp1 = (const float4*)g_kv + (ull)(p1 & 0x00FFFFFF) * 64;
        float4 k0 = kp0[lane];
        float4 k1 = kp1[lane];
        float4 v0 = kp0[32 + lane];
        float4 v1 = kp1[32 + lane];
        float d0 = qv.x * k0.x + qv.y * k0.y + qv.z * k0.z + qv.w * k0.w;
        float d1 = qv.x * k1.x + qv.y * k1.y + qv.z * k1.z + qv.w * k1.w;
        d0 += __shfl_xor_sync(0xffffffffu, d0, 1);
        d1 += __shfl_xor_sync(0xffffffffu, d1, 1);
        d0 += __shfl_xor_sync(0xffffffffu, d0, 2);
        d1 += __shfl_xor_sync(0xffffffffu, d1, 2);
        d0 += __shfl_xor_sync(0xffffffffu, d0, 4);
        d1 += __shfl_xor_sync(0xffffffffu, d1, 4);
        int st0 = p0 >> 24, st1 = p1 >> 24;
        float b0 = (st0 == 0) ? sb0 : (st0 == 1) ? sb1 : sb2;
        float b1 = (st1 == 0) ? sb0 : (st1 == 1) ? sb1 : sb2;
        float e0 = __expf(d0 + b0);
        float e1 = __expf(d1 + b1);
        s += e0 + e1;
        acc.x += e0 * v0.x + e1 * v1.x;
        acc.y += e0 * v0.y + e1 * v1.y;
        acc.z += e0 * v0.z + e1 * v1.z;
        acc.w += e0 * v0.w + e1 * v1.w;
    }
    if (i < end) {
        int p = g_edges[i];
        const float4* kp = (const float4*)g_kv + (ull)(p & 0x00FFFFFF) * 64;
        float4 kvv = kp[lane];
        float4 vv  = kp[32 + lane];
        float d = qv.x * kvv.x + qv.y * kvv.y + qv.z * kvv.z + qv.w * kvv.w;
        d += __shfl_xor_sync(0xffffffffu, d, 1);
        d += __shfl_xor_sync(0xffffffffu, d, 2);
        d += __shfl_xor_sync(0xffffffffu, d, 4);
        int st = p >> 24;
        float b = (st == 0) ? sb0 : (st == 1) ? sb1 : sb2;
        float e = __expf(d + b);
        s += e;
        acc.x += e * vv.x; acc.y += e * vv.y;
        acc.z += e * vv.z; acc.w += e * vv.w;
    }
    float inv = 1.f / (s + 1e-16f);
    float4 o = make_float4(acc.x * inv, acc.y * inv, acc.z * inv, acc.w * inv);
    ((float4*)g_attnout)[node * 32 + lane] = o;
}

// ---------------- final: y = attnout@Wo + bo + x ; LayerNorm(y) -> out ----
// LN done fully in registers: each row's 128 cols live across the 16 lanes of
// a tx-group (contiguous half-warp) -> shfl_xor {1,2,4,8} reduction.
__global__ __launch_bounds__(256)
void sgemm_ln_kernel(const float* __restrict__ Wo,
                     const float* __restrict__ bo,
                     const float* __restrict__ X,
                     const float* __restrict__ gamma,
                     const float* __restrict__ beta,
                     float* __restrict__ out) {
    __shared__ float As2[16][AS2_STRIDE];
    __shared__ float Bs[16][128];

    const int tid = threadIdx.x;
    const int tx = tid & 15;
    const int ty = tid >> 4;
    const int row0 = blockIdx.x * 128;

    GemmFrag F;
    gemm_mainloop(g_attnout, Wo, row0, F, As2, Bs);

    float4 bb0 = *(const float4*)&bo[tx * 8];
    float4 bb1 = *(const float4*)&bo[tx * 8 + 4];
    float4 g0  = *(const float4*)&gamma[tx * 8];
    float4 g1  = *(const float4*)&gamma[tx * 8 + 4];
    float4 be0 = *(const float4*)&beta[tx * 8];
    float4 be1 = *(const float4*)&beta[tx * 8 + 4];

    #pragma unroll
    for (int i = 0; i < 8; i++) {
        int r = row0 + ty * 8 + i;
        bool valid = (r < NN);
        float4 x0 = make_float4(0.f, 0.f, 0.f, 0.f), x1 = x0;
        if (valid) {
            x0 = *(const float4*)&X[r * 128 + tx * 8];
            x1 = *(const float4*)&X[r * 128 + tx * 8 + 4];
        }
        float2 p0 = unpack2(F.acc[i][0]);
        float2 p1 = unpack2(F.acc[i][1]);
        float2 p2 = unpack2(F.acc[i][2]);
        float2 p3 = unpack2(F.acc[i][3]);
        float y[8];
        y[0] = p0.x + bb0.x + x0.x;
        y[1] = p0.y + bb0.y + x0.y;
        y[2] = p1.x + bb0.z + x0.z;
        y[3] = p1.y + bb0.w + x0.w;
        y[4] = p2.x + bb1.x + x1.x;
        y[5] = p2.y + bb1.y + x1.y;
        y[6] = p3.x + bb1.z + x1.z;
        y[7] = p3.y + bb1.w + x1.w;
        float s1 = 0.f, s2 = 0.f;
        #pragma unroll
        for (int j = 0; j < 8; j++) { s1 += y[j]; s2 += y[j] * y[j]; }
        #pragma unroll
        for (int m = 1; m <= 8; m <<= 1) {
            s1 += __shfl_xor_sync(0xffffffffu, s1, m);
            s2 += __shfl_xor_sync(0xffffffffu, s2, m);
        }
        float mean = s1 * (1.f / 128.f);
        float var  = s2 * (1.f / 128.f) - mean * mean;
        float rstd = rsqrtf(var + LN_EPS);
        if (valid) {
            float4 o0, o1;
            o0.x = (y[0] - mean) * rstd * g0.x + be0.x;
            o0.y = (y[1] - mean) * rstd * g0.y + be0.y;
            o0.z = (y[2] - mean) * rstd * g0.z + be0.z;
            o0.w = (y[3] - mean) * rstd * g0.w + be0.w;
            o1.x = (y[4] - mean) * rstd * g1.x + be1.x;
            o1.y = (y[5] - mean) * rstd * g1.y + be1.y;
            o1.z = (y[6] - mean) * rstd * g1.z + be1.z;
            o1.w = (y[7] - mean) * rstd * g1.w + be1.w;
            *(float4*)&out[r * 128 + tx * 8]     = o0;
            *(float4*)&out[r * 128 + tx * 8 + 4] = o1;
        }
    }
}

// ---------------- launch ----------------
extern "C" void kernel_launch(void* const* d_in, const int* in_sizes, int n_in,
                              void* d_out, int out_size) {
    const float* x      = (const float*)d_in[0];
    const int*   stype  = (const int*)  d_in[1];
    const int*   ei     = (const int*)  d_in[2];
    const float* Wq     = (const float*)d_in[3];
    const float* bq     = (const float*)d_in[4];
    const float* Wk     = (const float*)d_in[5];
    const float* bk     = (const float*)d_in[6];
    const float* Wv     = (const float*)d_in[7];
    const float* bv     = (const float*)d_in[8];
    const float* sbias  = (const float*)d_in[9];
    const float* Wo     = (const float*)d_in[10];
    const float* bo     = (const float*)d_in[11];
    const float* gamma  = (const float*)d_in[12];
    const float* beta   = (const float*)d_in[13];
    float* out = (float*)d_out;

    const int gemm_blocks = (NN + 127) / 128;
    const int edge_blocks = (EE + 255) / 256;
    const int node_blocks = (NN + 255) / 256;

    // CSR build
    zero_kernel<<<node_blocks, 256>>>();
    hist_kernel<<<edge_blocks, 256>>>(ei);
    scan_kernel<<<1, 1024>>>();
    scatter_kernel<<<edge_blocks, 256>>>(ei, stype);

    // QKV projections (q pre-scaled by 1/sqrt(Hd); k,v interleaved per node)
    sgemm128_kernel<<<gemm_blocks, 256>>>(x, Wq, bq, 0, 128, INV_SQRT_HD);
    sgemm128_kernel<<<gemm_blocks, 256>>>(x, Wk, bk, 1, 256, 1.f);
    sgemm128_kernel<<<gemm_blocks, 256>>>(x, Wv, bv, 2, 256, 1.f);

    // fused segment softmax + aggregation (warp per dst node)
    attn_kernel<<<(NN * 32 + 255) / 256, 256>>>(sbias);

    // output projection + residual + layernorm (register LN, no smem staging)
    sgemm_ln_kernel<<<gemm_blocks, 256>>>(Wo, bo, x, gamma, beta, out);
}

// round 11
// speedup vs baseline: 1.2604x; 1.0991x over previous
#include <cuda_runtime.h>
#include <cuda_bf16.h>
#include <mma.h>
#include <cstdint>

using namespace nvcuda;

// Problem constants (fixed by the dataset)
#define NN   50000
#define NP   50048          // padded rows: 391 tiles * 128
#define EE   800000
#define CC   128
#define HEADS 4
#define HEAD_DIM 32
#define INV_SQRT_HD 0.17677669529663687f   // 1/sqrt(32)
#define LN_EPS 1e-5f

typedef unsigned long long ull;

// ---------------- device scratch (static, no allocation) ----------------
__device__ float g_q[NP * CC];          // q, pre-scaled by 1/sqrt(Hd)
__device__ float g_kv[NP * 2 * CC];     // interleaved [k(128) | v(128)] per node
__device__ float g_attnout[NP * CC];    // attention output
__device__ int   g_deg[NN];
__device__ int   g_cur[NN];
__device__ int   g_off[NN + 1];
__device__ int   g_edges[EE];           // packed: src | (structure_type << 24)
// W split-precision: [4 weights][k=128][n=128] bf16, same layout as input W.
// Wq copy is pre-scaled by 1/sqrt(Hd).
__device__ __nv_bfloat16 g_w_hi[4 * 128 * 128];
__device__ __nv_bfloat16 g_w_lo[4 * 128 * 128];

// ---------------- smem layout for wmma kernels ----------------
#define A_LD   136                       // bf16 elements per A row (pad)
#define SM_AH  0
#define SM_AL  (128 * A_LD * 2)          // 34816
#define SM_BIAS (2 * 128 * A_LD * 2)     // 69632 (float[16][136] replicated bias)
#define SM_TOTAL (SM_BIAS + 16 * 136 * 4)   // 78336
#define C_LD   132                       // float stride for O staging (aliases AH/AL)

// ---------------- zero counters ----------------
__global__ void zero_kernel() {
    int i = blockIdx.x * blockDim.x + threadIdx.x;
    if (i < NN) { g_deg[i] = 0; g_cur[i] = 0; }
}

// ---------------- histogram over dst ----------------
__global__ void hist_kernel(const int* __restrict__ ei) {
    int e = blockIdx.x * blockDim.x + threadIdx.x;
    if (e < EE) atomicAdd(&g_deg[ei[EE + e]], 1);
}

// ---------------- single-block exclusive scan of g_deg -> g_off ----------------
// (validated in R4/R5 runs — unchanged)
__global__ void scan_kernel() {
    __shared__ int wsum[32];
    __shared__ int s_carry;
    const int tid = threadIdx.x, lane = tid & 31, wid = tid >> 5;
    int carry = 0;
    for (int base = 0; base < NN; base += 1024) {
        int i = base + tid;
        int v = (i < NN) ? g_deg[i] : 0;
        int inc = v;
        #pragma unroll
        for (int d = 1; d < 32; d <<= 1) {
            int t = __shfl_up_sync(0xffffffffu, inc, d);
            if (lane >= d) inc += t;
        }
        if (lane == 31) wsum[wid] = inc;
        __syncthreads();
        if (wid == 0) {
            int w = wsum[lane];
            int wi = w;
            #pragma unroll
            for (int d = 1; d < 32; d <<= 1) {
                int t = __shfl_up_sync(0xffffffffu, wi, d);
                if (lane >= d) wi += t;
            }
            wsum[lane] = wi - w;   // exclusive warp offset
        }
        __syncthreads();
        int excl = carry + wsum[wid] + inc - v;
        if (i < NN) g_off[i] = excl;
        if (tid == 1023) s_carry = excl + v;
        __syncthreads();
        carry = s_carry;
    }
    if (tid == 0) g_off[NN] = carry;   // == EE
}

// ---------------- scatter edges into CSR (by dst), pack src+stype ----------------
__global__ void scatter_kernel(const int* __restrict__ ei,
                               const int* __restrict__ stype) {
    int e = blockIdx.x * blockDim.x + threadIdx.x;
    if (e >= EE) return;
    int s = ei[e];
    int d = ei[EE + e];
    int pos = atomicAdd(&g_cur[d], 1);
    g_edges[g_off[d] + pos] = s | (stype[s] << 24);
}

// ---------------- W split-precision prep (layout preserved: W[k][n]) -------
__global__ void wprep_kernel(const float* __restrict__ Wq, const float* __restrict__ Wk,
                             const float* __restrict__ Wv, const float* __restrict__ Wo) {
    int i = blockIdx.x * blockDim.x + threadIdx.x;   // 0 .. 65535
    int w = i >> 14;
    int idx = i & 16383;                             // k*128 + n
    const float* W = (w == 0) ? Wq : (w == 1) ? Wk : (w == 2) ? Wv : Wo;
    float v = W[idx] * ((w == 0) ? INV_SQRT_HD : 1.f);
    __nv_bfloat16 h = __float2bfloat16(v);
    g_w_hi[i] = h;
    g_w_lo[i] = __float2bfloat16(v - __bfloat162float(h));
}

// ---------------- shared: convert fp32 tile rows -> A_hi/A_lo bf16 smem -----
__device__ __forceinline__ void conv_A_tile(const float* __restrict__ A, int row0,
                                            char* sm, int tid) {
    int r = tid >> 1;                 // 0..127
    int c0 = (tid & 1) * 64;
    bool valid = (row0 + r) < NN;
    const float* xr = A + (size_t)(row0 + r) * 128 + c0;
    __nv_bfloat16* ah = (__nv_bfloat16*)(sm + SM_AH) + r * A_LD + c0;
    __nv_bfloat16* al = (__nv_bfloat16*)(sm + SM_AL) + r * A_LD + c0;
    #pragma unroll
    for (int c = 0; c < 64; c += 4) {
        float4 f = valid ? *(const float4*)(xr + c) : make_float4(0.f, 0.f, 0.f, 0.f);
        __nv_bfloat162 h01 = __floats2bfloat162_rn(f.x, f.y);
        __nv_bfloat162 h23 = __floats2bfloat162_rn(f.z, f.w);
        __nv_bfloat162 l01 = __floats2bfloat162_rn(f.x - __low2float(h01),
                                                   f.y - __high2float(h01));
        __nv_bfloat162 l23 = __floats2bfloat162_rn(f.z - __low2float(h23),
                                                   f.w - __high2float(h23));
        *(__nv_bfloat162*)(ah + c)     = h01;
        *(__nv_bfloat162*)(ah + c + 2) = h23;
        *(__nv_bfloat162*)(al + c)     = l01;
        *(__nv_bfloat162*)(al + c + 2) = l23;
    }
}

// build replicated bias tile: bias_f[16][136], every row == bias[0..127]
__device__ __forceinline__ void build_bias_tile(const float* __restrict__ bias,
                                                char* sm, int tid) {
    float* bf = (float*)(sm + SM_BIAS);
    for (int idx = tid; idx < 16 * 128; idx += 256) {
        int r = idx >> 7, c = idx & 127;
        bf[r * 136 + c] = __ldg(&bias[c]);
    }
}

typedef wmma::fragment<wmma::matrix_a, 16, 16, 16, __nv_bfloat16, wmma::row_major> FragA;
typedef wmma::fragment<wmma::matrix_b, 16, 16, 16, __nv_bfloat16, wmma::row_major> FragB;
typedef wmma::fragment<wmma::accumulator, 16, 16, 16, float> FragC;

// mainloop: acc[2][4] += split-bf16( A_smem x W[widx] ), warp tile 32x64
__device__ __forceinline__ void wmma_mainloop(FragC acc[2][4], const char* sm,
                                              int widx, int warp_m, int warp_n) {
    const __nv_bfloat16* Bh = g_w_hi + widx * 16384;
    const __nv_bfloat16* Bl = g_w_lo + widx * 16384;
    const __nv_bfloat16* Ah = (const __nv_bfloat16*)(sm + SM_AH);
    const __nv_bfloat16* Al = (const __nv_bfloat16*)(sm + SM_AL);
    for (int k = 0; k < 128; k += 16) {
        FragA ah[2], al[2];
        #pragma unroll
        for (int i = 0; i < 2; i++) {
            int ar = warp_m * 32 + i * 16;
            wmma::load_matrix_sync(ah[i], Ah + ar * A_LD + k, A_LD);
            wmma::load_matrix_sync(al[i], Al + ar * A_LD + k, A_LD);
        }
        #pragma unroll
        for (int j = 0; j < 4; j++) {
            int n0 = warp_n * 64 + j * 16;
            FragB bh, bl;
            wmma::load_matrix_sync(bh, Bh + k * 128 + n0, 128);
            wmma::load_matrix_sync(bl, Bl + k * 128 + n0, 128);
            #pragma unroll
            for (int i = 0; i < 2; i++) {
                wmma::mma_sync(acc[i][j], ah[i], bh, acc[i][j]);
                wmma::mma_sync(acc[i][j], al[i], bh, acc[i][j]);
                wmma::mma_sync(acc[i][j], ah[i], bl, acc[i][j]);
            }
        }
    }
}

// ---------------- fused QKV wmma GEMM: x tile -> q, k, v ---------------------
__global__ __launch_bounds__(256)
void qkv_wmma_kernel(const float* __restrict__ x,
                     const float* __restrict__ bq,
                     const float* __restrict__ bk,
                     const float* __restrict__ bv) {
    extern __shared__ char sm[];
    const int tid = threadIdx.x, wid = tid >> 5;
    const int warp_m = wid & 3;          // rows 32*warp_m
    const int warp_n = wid >> 2;         // cols 64*warp_n
    const int row0 = blockIdx.x * 128;

    conv_A_tile(x, row0, sm, tid);

    for (int widx = 0; widx < 3; widx++) {
        // q bias pre-scaled (Wq copy already pre-scaled in wprep)
        const float* bias = (widx == 0) ? bq : (widx == 1) ? bk : bv;
        __syncthreads();
        if (widx == 0) {
            float* bf = (float*)(sm + SM_BIAS);
            for (int idx = tid; idx < 16 * 128; idx += 256) {
                int r = idx >> 7, c = idx & 127;
                bf[r * 136 + c] = __ldg(&bias[c]) * INV_SQRT_HD;
            }
        } else {
            build_bias_tile(bias, sm, tid);
        }
        __syncthreads();

        FragC acc[2][4];
        const float* bf = (const float*)(sm + SM_BIAS);
        #pragma unroll
        for (int i = 0; i < 2; i++)
            #pragma unroll
            for (int j = 0; j < 4; j++)
                wmma::load_matrix_sync(acc[i][j], bf + warp_n * 64 + j * 16, 136,
                                       wmma::mem_row_major);

        wmma_mainloop(acc, sm, widx, warp_m, warp_n);

        float* outp = (widx == 0) ? g_q : (widx == 1) ? g_kv : (g_kv + 128);
        const int ld = (widx == 0) ? 128 : 256;
        #pragma unroll
        for (int i = 0; i < 2; i++)
            #pragma unroll
            for (int j = 0; j < 4; j++) {
                int r = row0 + warp_m * 32 + i * 16;      // padded buffers: OK to NP
                int n0 = warp_n * 64 + j * 16;
                wmma::store_matrix_sync(outp + (size_t)r * ld + n0, acc[i][j], ld,
                                        wmma::mem_row_major);
            }
    }
}

// ---------------- fused edge attention: one warp per dst node ----------------
__global__ __launch_bounds__(256)
void attn_kernel(const float* __restrict__ sbias) {
    int node = (blockIdx.x * blockDim.x + threadIdx.x) >> 5;
    if (node >= NN) return;
    const int lane = threadIdx.x & 31;
    const int head = lane >> 3;

    const float sb0 = __ldg(&sbias[0 * HEADS + head]);
    const float sb1 = __ldg(&sbias[1 * HEADS + head]);
    const float sb2 = __ldg(&sbias[2 * HEADS + head]);

    const float4 qv = ((const float4*)g_q)[node * 32 + lane];
    const int beg = g_off[node], end = g_off[node + 1];

    float s = 0.f;
    float4 acc = make_float4(0.f, 0.f, 0.f, 0.f);

    int i = beg;
    for (; i + 2 <= end; i += 2) {
        int p0 = g_edges[i];
        int p1 = g_edges[i + 1];
        const float4* kp0 = (const float4*)g_kv + (ull)(p0 & 0x00FFFFFF) * 64;
        const float4* kp1 = (const float4*)g_kv + (ull)(p1 & 0x00FFFFFF) * 64;
        float4 k0 = kp0[lane];
        float4 k1 = kp1[lane];
        float4 v0 = kp0[32 + lane];
        float4 v1 = kp1[32 + lane];
        float d0 = qv.x * k0.x + qv.y * k0.y + qv.z * k0.z + qv.w * k0.w;
        float d1 = qv.x * k1.x + qv.y * k1.y + qv.z * k1.z + qv.w * k1.w;
        d0 += __shfl_xor_sync(0xffffffffu, d0, 1);
        d1 += __shfl_xor_sync(0xffffffffu, d1, 1);
        d0 += __shfl_xor_sync(0xffffffffu, d0, 2);
        d1 += __shfl_xor_sync(0xffffffffu, d1, 2);
        d0 += __shfl_xor_sync(0xffffffffu, d0, 4);
        d1 += __shfl_xor_sync(0xffffffffu, d1, 4);
        int st0 = p0 >> 24, st1 = p1 >> 24;
        float b0 = (st0 == 0) ? sb0 : (st0 == 1) ? sb1 : sb2;
        float b1 = (st1 == 0) ? sb0 : (st1 == 1) ? sb1 : sb2;
        float e0 = __expf(d0 + b0);
        float e1 = __expf(d1 + b1);
        s += e0 + e1;
        acc.x += e0 * v0.x + e1 * v1.x;
        acc.y += e0 * v0.y + e1 * v1.y;
        acc.z += e0 * v0.z + e1 * v1.z;
        acc.w += e0 * v0.w + e1 * v1.w;
    }
    if (i < end) {
        int p = g_edges[i];
        const float4* kp = (const float4*)g_kv + (ull)(p & 0x00FFFFFF) * 64;
        float4 kvv = kp[lane];
        float4 vv  = kp[32 + lane];
        float d = qv.x * kvv.x + qv.y * kvv.y + qv.z * kvv.z + qv.w * kvv.w;
        d += __shfl_xor_sync(0xffffffffu, d, 1);
        d += __shfl_xor_sync(0xffffffffu, d, 2);
        d += __shfl_xor_sync(0xffffffffu, d, 4);
        int st = p >> 24;
        float b = (st == 0) ? sb0 : (st == 1) ? sb1 : sb2;
        float e = __expf(d + b);
        s += e;
        acc.x += e * vv.x; acc.y += e * vv.y;
        acc.z += e * vv.z; acc.w += e * vv.w;
    }
    float inv = 1.f / (s + 1e-16f);
    float4 o = make_float4(acc.x * inv, acc.y * inv, acc.z * inv, acc.w * inv);
    ((float4*)g_attnout)[node * 32 + lane] = o;
}

// ------- O-projection wmma GEMM + residual + LayerNorm ----------------------
__global__ __launch_bounds__(256)
void out_ln_kernel(const float* __restrict__ bo,
                   const float* __restrict__ X,
                   const float* __restrict__ gamma,
                   const float* __restrict__ beta,
                   float* __restrict__ out) {
    extern __shared__ char sm[];
    const int tid = threadIdx.x, wid = tid >> 5, lane = tid & 31;
    const int warp_m = wid & 3;
    const int warp_n = wid >> 2;
    const int row0 = blockIdx.x * 128;

    conv_A_tile(g_attnout, row0, sm, tid);
    build_bias_tile(bo, sm, tid);
    __syncthreads();

    FragC acc[2][4];
    const float* bf = (const float*)(sm + SM_BIAS);
    #pragma unroll
    for (int i = 0; i < 2; i++)
        #pragma unroll
        for (int j = 0; j < 4; j++)
            wmma::load_matrix_sync(acc[i][j], bf + warp_n * 64 + j * 16, 136,
                                   wmma::mem_row_major);

    wmma_mainloop(acc, sm, 3, warp_m, warp_n);

    // stage C into smem (reuses A region — all A reads are done)
    __syncthreads();
    float* Cst = (float*)(sm + SM_AH);
    #pragma unroll
    for (int i = 0; i < 2; i++)
        #pragma unroll
        for (int j = 0; j < 4; j++)
            wmma::store_matrix_sync(Cst + (warp_m * 32 + i * 16) * C_LD
                                        + warp_n * 64 + j * 16,
                                    acc[i][j], C_LD, wmma::mem_row_major);
    __syncthreads();

    // LayerNorm: warp per row, 16 rows per warp
    float4 g  = *(const float4*)&gamma[lane * 4];
    float4 bt = *(const float4*)&beta[lane * 4];
    for (int rr = wid * 16; rr < wid * 16 + 16; rr++) {
        int r = row0 + rr;
        if (r >= NN) continue;
        float4 cv = *(const float4*)&Cst[rr * C_LD + lane * 4];
        float4 xv = *(const float4*)&X[(size_t)r * 128 + lane * 4];
        float4 y = make_float4(cv.x + xv.x, cv.y + xv.y, cv.z + xv.z, cv.w + xv.w);
        float s1 = y.x + y.y + y.z + y.w;
        float s2 = y.x * y.x + y.y * y.y + y.z * y.z + y.w * y.w;
        #pragma unroll
        for (int m = 16; m >= 1; m >>= 1) {
            s1 += __shfl_xor_sync(0xffffffffu, s1, m);
            s2 += __shfl_xor_sync(0xffffffffu, s2, m);
        }
        float mean = s1 * (1.f / 128.f);
        float var  = s2 * (1.f / 128.f) - mean * mean;
        float rstd = rsqrtf(var + LN_EPS);
        float4 o;
        o.x = (y.x - mean) * rstd * g.x + bt.x;
        o.y = (y.y - mean) * rstd * g.y + bt.y;
        o.z = (y.z - mean) * rstd * g.z + bt.z;
        o.w = (y.w - mean) * rstd * g.w + bt.w;
        *(float4*)&out[(size_t)r * 128 + lane * 4] = o;
    }
}

// ---------------- launch ----------------
extern "C" void kernel_launch(void* const* d_in, const int* in_sizes, int n_in,
                              void* d_out, int out_size) {
    const float* x      = (const float*)d_in[0];
    const int*   stype  = (const int*)  d_in[1];
    const int*   ei     = (const int*)  d_in[2];
    const float* Wq     = (const float*)d_in[3];
    const float* bq     = (const float*)d_in[4];
    const float* Wk     = (const float*)d_in[5];
    const float* bk     = (const float*)d_in[6];
    const float* Wv     = (const float*)d_in[7];
    const float* bv     = (const float*)d_in[8];
    const float* sbias  = (const float*)d_in[9];
    const float* Wo     = (const float*)d_in[10];
    const float* bo     = (const float*)d_in[11];
    const float* gamma  = (const float*)d_in[12];
    const float* beta   = (const float*)d_in[13];
    float* out = (float*)d_out;

    // Unconditional, deterministic, capture-safe (not a stream op).
    cudaFuncSetAttribute(qkv_wmma_kernel, cudaFuncAttributeMaxDynamicSharedMemorySize, SM_TOTAL);
    cudaFuncSetAttribute(out_ln_kernel,   cudaFuncAttributeMaxDynamicSharedMemorySize, SM_TOTAL);

    const int tile_blocks = (NN + 127) / 128;   // 391
    const int edge_blocks = (EE + 255) / 256;
    const int node_blocks = (NN + 255) / 256;

    // CSR build
    zero_kernel<<<node_blocks, 256>>>();
    hist_kernel<<<edge_blocks, 256>>>(ei);
    scan_kernel<<<1, 1024>>>();
    scatter_kernel<<<edge_blocks, 256>>>(ei, stype);

    // weight split-precision prep (4 x 128 x 128, Wq pre-scaled)
    wprep_kernel<<<256, 256>>>(Wq, Wk, Wv, Wo);

    // fused QKV projections on HMMA tensor cores (split-bf16)
    qkv_wmma_kernel<<<tile_blocks, 256, SM_TOTAL>>>(x, bq, bk, bv);

    // fused segment softmax + aggregation (warp per dst node)
    attn_kernel<<<(NN * 32 + 255) / 256, 256>>>(sbias);

    // output projection + residual + layernorm on HMMA tensor cores
    out_ln_kernel<<<tile_blocks, 256, SM_TOTAL>>>(bo, x, gamma, beta, out);
}